// round 12
// baseline (speedup 1.0000x reference)
#include <cuda_runtime.h>
#include <cuda_fp16.h>
#include <cstdint>

// ---------------- problem constants ----------------
#define T_TOK 8192
#define G_GRP 8
#define K_DIM 1024
#define N_DIM 2048

// ---------------- scratch (fp16) ----------------
__device__ __half g_xh[(size_t)T_TOK * K_DIM];            // [T, 1024]  16MB
__device__ __half g_wh[(size_t)G_GRP * N_DIM * K_DIM];    // [G*N, 1024] 32MB

// ---------------- conversion kernel (x and w in one launch) ----------------
__global__ void convert_fp16(const float* __restrict__ x,
                             const float* __restrict__ w)
{
    const size_t XE = (size_t)T_TOK * K_DIM;                 // 8.39M (mult of 8)
    const size_t WE = (size_t)G_GRP * N_DIM * K_DIM;         // 16.8M
    size_t i = ((size_t)blockIdx.x * blockDim.x + threadIdx.x) * 8;
    const float* src;
    __half* dst;
    size_t off;
    if (i < XE) { src = x; dst = g_xh; off = i; }
    else        { off = i - XE; if (off >= WE) return; src = w; dst = g_wh; }
    const float4 v0 = *reinterpret_cast<const float4*>(src + off);
    const float4 v1 = *reinterpret_cast<const float4*>(src + off + 4);
    union { __half h[8]; uint4 u; } P;
    P.h[0] = __float2half_rn(v0.x); P.h[1] = __float2half_rn(v0.y);
    P.h[2] = __float2half_rn(v0.z); P.h[3] = __float2half_rn(v0.w);
    P.h[4] = __float2half_rn(v1.x); P.h[5] = __float2half_rn(v1.y);
    P.h[6] = __float2half_rn(v1.z); P.h[7] = __float2half_rn(v1.w);
    *reinterpret_cast<uint4*>(dst + off) = P.u;
}

// ---------------- PTX helpers (baseline features only) ----------------
__device__ __forceinline__ uint32_t smem_u32(const void* p) {
    uint32_t a;
    asm("{ .reg .u64 t; cvta.to.shared.u64 t, %1; cvt.u32.u64 %0, t; }"
        : "=r"(a) : "l"(p));
    return a;
}
__device__ __forceinline__ void cp16(uint32_t dst, const void* src) {
    asm volatile("cp.async.cg.shared.global [%0], [%1], 16;" :: "r"(dst), "l"(src));
}
#define CP_COMMIT() asm volatile("cp.async.commit_group;" ::: "memory")
#define CP_WAIT1()  asm volatile("cp.async.wait_group 1;" ::: "memory")

__device__ __forceinline__ void ldsm_x4(uint32_t& r0, uint32_t& r1,
                                        uint32_t& r2, uint32_t& r3, uint32_t a) {
    asm volatile("ldmatrix.sync.aligned.m8n8.x4.shared.b16 {%0,%1,%2,%3}, [%4];"
                 : "=r"(r0), "=r"(r1), "=r"(r2), "=r"(r3) : "r"(a));
}
__device__ __forceinline__ void mma_16816(float* c, const uint32_t* a,
                                          const uint32_t* b) {
    asm volatile(
        "mma.sync.aligned.m16n8k16.row.col.f32.f16.f16.f32 "
        "{%0,%1,%2,%3}, {%4,%5,%6,%7}, {%8,%9}, {%0,%1,%2,%3};"
        : "+f"(c[0]), "+f"(c[1]), "+f"(c[2]), "+f"(c[3])
        : "r"(a[0]), "r"(a[1]), "r"(a[2]), "r"(a[3]), "r"(b[0]), "r"(b[1]));
}

// ---------------- GEMM kernel (persistent, group-aligned tiles) ----------------
constexpr int BM = 128, BN = 128, BK = 64;
constexpr int TILE = BM * 128;                    // 16384 bytes (A or B tile)
constexpr int STAGE_BYTES = 2 * TILE;             // 32768
constexpr int STAGES = 3;
constexpr int SMEM_TOTAL = STAGES * STAGE_BYTES;  // 98304 -> 2 CTAs/SM
constexpr int NITER = K_DIM / BK;                 // 16

// sw128 swizzle for 128-byte rows: 16B chunk c at row r lands at chunk c^(r&7)
__device__ __forceinline__ uint32_t swz(uint32_t row, uint32_t chunk) {
    return row * 128u + ((chunk ^ (row & 7u)) << 4);
}

__global__ __launch_bounds__(256, 2)
void grouped_gemm_hmma(const int* __restrict__ offs, float* __restrict__ out)
{
    const int tid  = threadIdx.x;
    const int wid  = tid >> 5;
    const int lane = tid & 31;

    // warp grid 2 (m) x 4 (n): warp tile 64x32
    const int WM0 = (wid >> 2) * 64;
    const int WN0 = (wid & 3) * 32;
    const int c8 = tid & 7;
    const int r0 = tid >> 3;

    extern __shared__ __align__(1024) char smem[];
    const uint32_t sb = smem_u32(smem);

    // group row-tile counts (group-aligned: exact non-overlapping cover)
    int cnt[G_GRP], base[G_GRP], lo_[G_GRP], hi_[G_GRP];
    int NP = 0;
#pragma unroll
    for (int gg = 0; gg < G_GRP; gg++) {
        const int l = gg ? __ldg(offs + gg - 1) : 0;
        const int h = __ldg(offs + gg);
        lo_[gg] = l; hi_[gg] = h;
        cnt[gg] = (h - l + BM - 1) >> 7;
        base[gg] = NP;
        NP += cnt[gg];
    }
    const int NT = NP * 16;     // total (row-tile, n-tile) pairs

#pragma unroll 1
    for (int t = blockIdx.x; t < NT; t += gridDim.x) {
        const int pair = t >> 4;
        const int nt   = t & 15;
        int g = 0;
#pragma unroll
        for (int gg = 0; gg < G_GRP; gg++)
            if (pair >= base[gg] && pair < base[gg] + cnt[gg]) g = gg;
        const int start = lo_[g] + ((pair - base[g]) << 7);
        const int hi    = hi_[g];
        const int n0    = nt * BN;

        __syncthreads();   // all warps done reading smem of the previous tile

        // per-j row pointers; A rows clamped to T-1 (tail rows loaded, never stored)
        const __half* aP[4];
        const __half* bP[4];
#pragma unroll
        for (int j = 0; j < 4; j++) {
            int r = start + r0 + 32 * j;
            if (r > T_TOK - 1) r = T_TOK - 1;
            aP[j] = g_xh + (size_t)r * K_DIM + c8 * 8;
            bP[j] = g_wh + ((size_t)g * N_DIM + n0 + r0 + 32 * j) * K_DIM + c8 * 8;
        }

        auto load_stage = [&](int s) {
            const int kb = s * BK;
            const uint32_t bb = sb + (uint32_t)(s % STAGES) * STAGE_BYTES;
#pragma unroll
            for (int j = 0; j < 4; j++) {
                const uint32_t row = (uint32_t)r0 + 32u * j;
                const uint32_t so  = swz(row, c8);
                cp16(bb + so,        aP[j] + kb);
                cp16(bb + TILE + so, bP[j] + kb);
            }
        };

        float acc[4][4][4];
#pragma unroll
        for (int i = 0; i < 4; i++)
#pragma unroll
            for (int j = 0; j < 4; j++)
#pragma unroll
                for (int q = 0; q < 4; q++) acc[i][j][q] = 0.0f;

        load_stage(0); CP_COMMIT();
        load_stage(1); CP_COMMIT();

#pragma unroll 1
        for (int it = 0; it < NITER; it++) {
            CP_WAIT1();      // stage `it` resident (prior tile's empties drain FIFO)
            __syncthreads();

            if (it + 2 < NITER) load_stage(it + 2);
            CP_COMMIT();     // unconditional: uniform group counting

            const uint32_t aT = sb + (uint32_t)(it % STAGES) * STAGE_BYTES;
            const uint32_t bT = aT + TILE;

#pragma unroll
            for (int ks = 0; ks < BK / 16; ks++) {   // 4 k16 steps
                const uint32_t cA = 2u * ks;
                uint32_t a[4][4], b[4][2];
#pragma unroll
                for (int i = 0; i < 4; i++) {
                    const uint32_t row = (uint32_t)(WM0 + i * 16 + (lane & 15));
                    const uint32_t ch  = cA + (uint32_t)(lane >> 4);
                    ldsm_x4(a[i][0], a[i][1], a[i][2], a[i][3], aT + swz(row, ch));
                }
#pragma unroll
                for (int jp = 0; jp < 2; jp++) {     // x4 covers a j-pair
                    const uint32_t row = (uint32_t)(WN0 + (jp * 2 + ((lane >> 4) & 1)) * 8
                                                    + (lane & 7));
                    const uint32_t ch  = cA + ((uint32_t)(lane >> 3) & 1u);
                    ldsm_x4(b[jp * 2][0], b[jp * 2][1],
                            b[jp * 2 + 1][0], b[jp * 2 + 1][1], bT + swz(row, ch));
                }
#pragma unroll
                for (int i = 0; i < 4; i++)
#pragma unroll
                    for (int j = 0; j < 4; j++)
                        mma_16816(acc[i][j], a[i], b[j]);
            }
        }

        // ---- epilogue: fp32 stores, clip rows to [start, hi) ----
        const int rbase = start + WM0 + (lane >> 2);
        const int cbase = n0 + WN0 + (lane & 3) * 2;
#pragma unroll
        for (int i = 0; i < 4; i++) {
            const int ra = rbase + i * 16;
            const int rb = ra + 8;
            const bool wa = (ra < hi);
            const bool wb = (rb < hi);
            float* pa = out + (size_t)ra * N_DIM + cbase;
            float* pb = out + (size_t)rb * N_DIM + cbase;
#pragma unroll
            for (int j = 0; j < 4; j++) {
                if (wa) *reinterpret_cast<float2*>(pa + j * 8) =
                    make_float2(acc[i][j][0], acc[i][j][1]);
                if (wb) *reinterpret_cast<float2*>(pb + j * 8) =
                    make_float2(acc[i][j][2], acc[i][j][3]);
            }
        }
    }
}

// ---------------- launch ----------------
extern "C" void kernel_launch(void* const* d_in, const int* in_sizes, int n_in,
                              void* d_out, int out_size) {
    const float* x    = (const float*)d_in[0];  // [T, K]
    const float* w    = (const float*)d_in[1];  // [G, N, K]
    const int*   offs = (const int*)d_in[2];    // [G]
    float* out = (float*)d_out;                 // [T, N]

    static int nCTA = 0;
    if (nCTA == 0) {
        int sms = 0, dev = 0;
        cudaGetDevice(&dev);
        cudaDeviceGetAttribute(&sms, cudaDevAttrMultiProcessorCount, dev);
        nCTA = 2 * sms;   // all co-resident (2/SM by smem+regs)
        cudaFuncSetAttribute(grouped_gemm_hmma,
                             cudaFuncAttributeMaxDynamicSharedMemorySize,
                             SMEM_TOTAL);
    }

    // single conversion launch covering x then w (both counts divisible by 8)
    {
        const size_t total8 = ((size_t)T_TOK * K_DIM + (size_t)G_GRP * N_DIM * K_DIM) / 8;
        const int threads = 256;
        const int blocks = (int)((total8 + threads - 1) / threads);  // 12288
        convert_fp16<<<blocks, threads>>>(x, w);
    }

    grouped_gemm_hmma<<<nCTA, 256, SMEM_TOTAL>>>(offs, out);
}

// round 13
// speedup vs baseline: 1.0221x; 1.0221x over previous
#include <cuda_runtime.h>
#include <cuda_fp16.h>
#include <cstdint>

// ---------------- problem constants ----------------
#define T_TOK 8192
#define G_GRP 8
#define K_DIM 1024
#define N_DIM 2048

// ---------------- scratch (fp16) ----------------
__device__ __half g_xh[(size_t)T_TOK * K_DIM];            // [T, 1024]  16MB
__device__ __half g_wh[(size_t)G_GRP * N_DIM * K_DIM];    // [G*N, 1024] 32MB

// ---------------- conversion kernel (x and w in one launch) ----------------
__global__ void convert_fp16(const float* __restrict__ x,
                             const float* __restrict__ w)
{
    // allow the dependent GEMM grid to begin launching immediately; its
    // cudaGridDependencySynchronize still waits for this grid's completion.
    cudaTriggerProgrammaticLaunchCompletion();

    const size_t XE = (size_t)T_TOK * K_DIM;                 // 8.39M (mult of 8)
    const size_t WE = (size_t)G_GRP * N_DIM * K_DIM;         // 16.8M
    size_t i = ((size_t)blockIdx.x * blockDim.x + threadIdx.x) * 8;
    const float* src;
    __half* dst;
    size_t off;
    if (i < XE) { src = x; dst = g_xh; off = i; }
    else        { off = i - XE; if (off >= WE) return; src = w; dst = g_wh; }
    const float4 v0 = *reinterpret_cast<const float4*>(src + off);
    const float4 v1 = *reinterpret_cast<const float4*>(src + off + 4);
    union { __half h[8]; uint4 u; } P;
    P.h[0] = __float2half_rn(v0.x); P.h[1] = __float2half_rn(v0.y);
    P.h[2] = __float2half_rn(v0.z); P.h[3] = __float2half_rn(v0.w);
    P.h[4] = __float2half_rn(v1.x); P.h[5] = __float2half_rn(v1.y);
    P.h[6] = __float2half_rn(v1.z); P.h[7] = __float2half_rn(v1.w);
    *reinterpret_cast<uint4*>(dst + off) = P.u;
}

// ---------------- PTX helpers (baseline features only) ----------------
__device__ __forceinline__ uint32_t smem_u32(const void* p) {
    uint32_t a;
    asm("{ .reg .u64 t; cvta.to.shared.u64 t, %1; cvt.u32.u64 %0, t; }"
        : "=r"(a) : "l"(p));
    return a;
}
__device__ __forceinline__ void cp16(uint32_t dst, const void* src) {
    asm volatile("cp.async.cg.shared.global [%0], [%1], 16;" :: "r"(dst), "l"(src));
}
#define CP_COMMIT() asm volatile("cp.async.commit_group;" ::: "memory")
#define CP_WAIT1()  asm volatile("cp.async.wait_group 1;" ::: "memory")

__device__ __forceinline__ void ldsm_x4(uint32_t& r0, uint32_t& r1,
                                        uint32_t& r2, uint32_t& r3, uint32_t a) {
    asm volatile("ldmatrix.sync.aligned.m8n8.x4.shared.b16 {%0,%1,%2,%3}, [%4];"
                 : "=r"(r0), "=r"(r1), "=r"(r2), "=r"(r3) : "r"(a));
}
__device__ __forceinline__ void mma_16816(float* c, const uint32_t* a,
                                          const uint32_t* b) {
    asm volatile(
        "mma.sync.aligned.m16n8k16.row.col.f32.f16.f16.f32 "
        "{%0,%1,%2,%3}, {%4,%5,%6,%7}, {%8,%9}, {%0,%1,%2,%3};"
        : "+f"(c[0]), "+f"(c[1]), "+f"(c[2]), "+f"(c[3])
        : "r"(a[0]), "r"(a[1]), "r"(a[2]), "r"(a[3]), "r"(b[0]), "r"(b[1]));
}

// ---------------- GEMM kernel ----------------
// Group-aligned row tiles: row tile t of group g covers rows
// [lo_g + 128*t, min(lo_g + 128*(t+1), hi_g)) -- exact non-overlapping cover.
constexpr int BM = 128, BN = 128, BK = 64;
constexpr int TILE = BM * 128;                    // 16384 bytes (A or B tile)
constexpr int STAGE_BYTES = 2 * TILE;             // 32768
constexpr int STAGES = 3;
constexpr int SMEM_TOTAL = STAGES * STAGE_BYTES;  // 98304 -> 2 CTAs/SM
constexpr int NITER = K_DIM / BK;                 // 16
constexpr int MAX_RT = T_TOK / BM + G_GRP;        // 72 (upper bound on row tiles)

// sw128 swizzle for 128-byte rows: 16B chunk c at row r lands at chunk c^(r&7)
__device__ __forceinline__ uint32_t swz(uint32_t row, uint32_t chunk) {
    return row * 128u + ((chunk ^ (row & 7u)) << 4);
}

__global__ __launch_bounds__(256, 2)
void grouped_gemm_hmma(const int* __restrict__ offs, float* __restrict__ out)
{
    // map blockIdx.y -> (group, group-aligned row tile)
    // (offs is a harness input, not written by convert_fp16 -> safe pre-sync)
    const int rid = blockIdx.y;
    int g = -1, start = 0, hi = 0;
    {
        int a = 0;
#pragma unroll
        for (int gg = 0; gg < G_GRP; gg++) {
            const int l = gg ? __ldg(offs + gg - 1) : 0;
            const int h = __ldg(offs + gg);
            const int c = (h - l + BM - 1) >> 7;   // ceil(cnt/128)
            if (rid >= a && rid < a + c) { g = gg; start = l + ((rid - a) << 7); hi = h; }
            a += c;
        }
    }
    if (g < 0) {
        // still must participate in the grid dependency before exiting
        cudaGridDependencySynchronize();
        return;
    }
    const int n0 = blockIdx.x * BN;

    extern __shared__ __align__(1024) char smem[];
    const uint32_t sb = smem_u32(smem);

    const int tid  = threadIdx.x;
    const int wid  = tid >> 5;
    const int lane = tid & 31;

    // warp grid 2 (m) x 4 (n): warp tile 64x32
    const int WM0 = (wid >> 2) * 64;
    const int WN0 = (wid & 3) * 32;

    // ---- cp.async mapping: per tile 128 rows x 8 chunks = 1024; A+B = 8/thread
    const int c8 = tid & 7;
    const int r0 = tid >> 3;
    // precomputed per-j row pointers; A rows clamped to T-1 (tail tiles may
    // reach past hi/T; clamped rows are loaded but never stored)
    const __half* aP[4];
    const __half* bP[4];
#pragma unroll
    for (int j = 0; j < 4; j++) {
        int r = start + r0 + 32 * j;
        if (r > T_TOK - 1) r = T_TOK - 1;
        aP[j] = g_xh + (size_t)r * K_DIM + c8 * 8;
        bP[j] = g_wh + ((size_t)g * N_DIM + n0 + r0 + 32 * j) * K_DIM + c8 * 8;
    }

    auto load_stage = [&](int s) {
        const int kb = s * BK;
        const uint32_t base = sb + (uint32_t)(s % STAGES) * STAGE_BYTES;
#pragma unroll
        for (int j = 0; j < 4; j++) {
            const uint32_t row = (uint32_t)r0 + 32u * j;
            const uint32_t so  = swz(row, c8);
            cp16(base + so,        aP[j] + kb);
            cp16(base + TILE + so, bP[j] + kb);
        }
    };

    float acc[4][4][4];
#pragma unroll
    for (int i = 0; i < 4; i++)
#pragma unroll
        for (int j = 0; j < 4; j++)
#pragma unroll
            for (int q = 0; q < 4; q++) acc[i][j][q] = 0.0f;

    // wait for the conversion grid's writes to be visible, then start loads
    cudaGridDependencySynchronize();

    load_stage(0); CP_COMMIT();
    load_stage(1); CP_COMMIT();

    for (int it = 0; it < NITER; it++) {
        CP_WAIT1();          // stage `it` resident
        __syncthreads();     // all warps done with buf (it+2)%3 (= it-1)

        if (it + 2 < NITER) load_stage(it + 2);
        CP_COMMIT();         // unconditional: uniform group counting

        const uint32_t aT = sb + (uint32_t)(it % STAGES) * STAGE_BYTES;
        const uint32_t bT = aT + TILE;

#pragma unroll
        for (int ks = 0; ks < BK / 16; ks++) {   // 4 k16 steps
            const uint32_t cA = 2u * ks;
            uint32_t a[4][4], b[4][2];
#pragma unroll
            for (int i = 0; i < 4; i++) {
                const uint32_t row = (uint32_t)(WM0 + i * 16 + (lane & 15));
                const uint32_t ch  = cA + (uint32_t)(lane >> 4);
                ldsm_x4(a[i][0], a[i][1], a[i][2], a[i][3], aT + swz(row, ch));
            }
#pragma unroll
            for (int jp = 0; jp < 2; jp++) {     // x4 covers a j-pair
                const uint32_t row = (uint32_t)(WN0 + (jp * 2 + ((lane >> 4) & 1)) * 8
                                                + (lane & 7));
                const uint32_t ch  = cA + ((uint32_t)(lane >> 3) & 1u);
                ldsm_x4(b[jp * 2][0], b[jp * 2][1],
                        b[jp * 2 + 1][0], b[jp * 2 + 1][1], bT + swz(row, ch));
            }
#pragma unroll
            for (int i = 0; i < 4; i++)
#pragma unroll
                for (int j = 0; j < 4; j++)
                    mma_16816(acc[i][j], a[i], b[j]);
        }
    }

    // ---- epilogue: fp32 stores, clip rows to [start, hi) ----
    const int rbase = start + WM0 + (lane >> 2);
    const int cbase = n0 + WN0 + (lane & 3) * 2;
#pragma unroll
    for (int i = 0; i < 4; i++) {
        const int ra = rbase + i * 16;
        const int rb = ra + 8;
        const bool wa = (ra < hi);
        const bool wb = (rb < hi);
        float* pa = out + (size_t)ra * N_DIM + cbase;
        float* pb = out + (size_t)rb * N_DIM + cbase;
#pragma unroll
        for (int j = 0; j < 4; j++) {
            if (wa) *reinterpret_cast<float2*>(pa + j * 8) =
                make_float2(acc[i][j][0], acc[i][j][1]);
            if (wb) *reinterpret_cast<float2*>(pb + j * 8) =
                make_float2(acc[i][j][2], acc[i][j][3]);
        }
    }
}

// ---------------- launch ----------------
extern "C" void kernel_launch(void* const* d_in, const int* in_sizes, int n_in,
                              void* d_out, int out_size) {
    const float* x    = (const float*)d_in[0];  // [T, K]
    const float* w    = (const float*)d_in[1];  // [G, N, K]
    const int*   offs = (const int*)d_in[2];    // [G]
    float* out = (float*)d_out;                 // [T, N]

    static bool inited = false;
    if (!inited) {
        cudaFuncSetAttribute(grouped_gemm_hmma,
                             cudaFuncAttributeMaxDynamicSharedMemorySize,
                             SMEM_TOTAL);
        inited = true;
    }

    // conversion (x then w in one grid)
    {
        const size_t total8 = ((size_t)T_TOK * K_DIM + (size_t)G_GRP * N_DIM * K_DIM) / 8;
        const int threads = 256;
        const int blocks = (int)((total8 + threads - 1) / threads);  // 12288
        convert_fp16<<<blocks, threads>>>(x, w);
    }

    // GEMM with programmatic dependent launch: overlaps its launch/prologue
    // with the conversion grid's tail; data wait happens in-kernel.
    {
        cudaLaunchConfig_t cfg = {};
        cfg.gridDim = dim3(N_DIM / BN, MAX_RT, 1);   // 16 x 72
        cfg.blockDim = dim3(256, 1, 1);
        cfg.dynamicSmemBytes = SMEM_TOTAL;
        cfg.stream = 0;
        cudaLaunchAttribute attr[1];
        attr[0].id = cudaLaunchAttributeProgrammaticStreamSerialization;
        attr[0].val.programmaticStreamSerializationAllowed = 1;
        cfg.attrs = attr;
        cfg.numAttrs = 1;
        cudaLaunchKernelEx(&cfg, grouped_gemm_hmma, offs, out);
    }
}